// round 2
// baseline (speedup 1.0000x reference)
#include <cuda_runtime.h>
#include <cuda_bf16.h>

#define FM      14
#define HW      196          // 14*14
#define CH      2048
#define CHUNKS  16
#define CPC     (CH / CHUNKS)   // 128 channels per chunk
#define NWIN    361
#define MAXB    64

#define NEG_INF __int_as_float(0xff800000)

// Partial channel sums: [chunk][batch][hw]. No zero-init needed (fully overwritten).
__device__ float g_part[CHUNKS * MAXB * HW];

// ---------------------------------------------------------------------------
// Kernel 1: channel-sum reduction. One block = (batch, channel-chunk).
// 196 threads = 4 channel-groups x 49 float4 lanes. LDG.128, fully coalesced.
// ---------------------------------------------------------------------------
__global__ __launch_bounds__(196) void chan_sum_kernel(const float* __restrict__ x, int B) {
    const int b     = blockIdx.x;
    const int chunk = blockIdx.y;
    const int tid   = threadIdx.x;          // 0..195
    const int grp   = tid / 49;             // 0..3  (channel sub-slice)
    const int v     = tid - grp * 49;       // 0..48 (float4 index within a 196-float row)

    const float4* base = reinterpret_cast<const float4*>(
        x + ((size_t)b * CH + (size_t)chunk * CPC) * HW);

    float4 acc = make_float4(0.f, 0.f, 0.f, 0.f);
#pragma unroll 8
    for (int c = grp; c < CPC; c += 4) {
        float4 t = base[c * 49 + v];
        acc.x += t.x; acc.y += t.y; acc.z += t.z; acc.w += t.w;
    }

    __shared__ float4 red[4 * 49];
    red[grp * 49 + v] = acc;
    __syncthreads();

    if (tid < HW) {
        const float* rf = reinterpret_cast<const float*>(red);
        float s = rf[tid] + rf[HW + tid] + rf[2 * HW + tid] + rf[3 * HW + tid];
        g_part[(chunk * B + b) * HW + tid] = s;
    }
}

// ---------------------------------------------------------------------------
// Kernel 2: finalize sums, window scores, greedy NMS, write all outputs.
// One block per batch, 384 threads. Warps 0..2 handle NMS groups 0..2.
// Output layout (fp32): [B*7 indices][B*7 window scores][B*361 all_scores]
// ---------------------------------------------------------------------------
__device__ __forceinline__ float pick4(const float a[4], int kk) {
    float r = a[0];
    if (kk == 1) r = a[1];
    if (kk == 2) r = a[2];
    if (kk == 3) r = a[3];
    return r;
}

__global__ __launch_bounds__(384) void appm_finalize_kernel(
    const int* __restrict__ coords, float* __restrict__ out, int B)
{
    const int b   = blockIdx.x;
    const int tid = threadIdx.x;

    __shared__ float ssum[HW];
    __shared__ float scores[NWIN];
    __shared__ float cbox[NWIN * 4];
    __shared__ int   sel_idx[7];
    __shared__ float sel_sc[7];

    // 1. Sum the 16 partials.
    if (tid < HW) {
        float s = 0.f;
#pragma unroll
        for (int k = 0; k < CHUNKS; k++) s += g_part[(k * B + b) * HW + tid];
        ssum[tid] = s;
    }
    // Load coordinates as floats (exact: all values <= 448).
    for (int i = tid; i < NWIN * 4; i += blockDim.x) cbox[i] = (float)coords[i];
    __syncthreads();

    // 2. Window scores (avg-pool over each sliding window).
    float* all_scores_out = out + 14 * B;   // after indices[ B*7 ] + scores[ B*7 ]
    for (int w = tid; w < NWIN; w += blockDim.x) {
        int i, j, rh, rw;
        if (w < 121)      { rh = 4; rw = 4; int l = w;        i = l / 11; j = l % 11; }
        else if (w < 241) { rh = 3; rw = 5; int l = w - 121;  i = l / 10; j = l % 10; }
        else              { rh = 5; rw = 3; int l = w - 241;  i = l / 12; j = l % 12; }
        float s = 0.f;
        for (int di = 0; di < rh; di++)
            for (int dj = 0; dj < rw; dj++)
                s += ssum[(i + di) * FM + (j + dj)];
        s /= (float)(rh * rw);
        scores[w] = s;
        all_scores_out[b * NWIN + w] = s;
    }
    __syncthreads();

    // 3. Greedy NMS: warp g handles group g.
    const int wid  = tid >> 5;
    const int lane = tid & 31;
    if (wid < 3) {
        const int starts[3]  = {0, 121, 241};
        const int counts[3]  = {121, 120, 120};
        const int ns[3]      = {2, 3, 2};
        const int outoff[3]  = {0, 2, 5};
        const float thresh   = 0.25f;

        const int st  = starts[wid];
        const int cnt = counts[wid];
        const int n   = ns[wid];

        float sc[4], x0[4], y0[4], x1[4], y1[4];
        bool  alive[4];
#pragma unroll
        for (int k = 0; k < 4; k++) {
            int ii = k * 32 + lane;
            bool valid = (ii < cnt);
            alive[k] = valid;
            int gi = st + (valid ? ii : 0);
            sc[k] = valid ? scores[gi] : 0.f;
            x0[k] = cbox[gi * 4 + 0];
            y0[k] = cbox[gi * 4 + 1];
            x1[k] = cbox[gi * 4 + 2];
            y1[k] = cbox[gi * 4 + 3];
        }

        for (int step = 0; step < n; step++) {
            // argmax over where(alive, sc, -inf); first-index tie-break.
            float bv = NEG_INF;
            int   bi = 0x7FFFFFFF;   // relative index within group
#pragma unroll
            for (int k = 0; k < 4; k++) {
                float vkv = alive[k] ? sc[k] : NEG_INF;
                int   vki = k * 32 + lane;
                if (vki < cnt && (vkv > bv || (vkv == bv && vki < bi))) { bv = vkv; bi = vki; }
            }
#pragma unroll
            for (int off = 16; off > 0; off >>= 1) {
                float ov = __shfl_down_sync(0xFFFFFFFFu, bv, off);
                int   oi = __shfl_down_sync(0xFFFFFFFFu, bi, off);
                if (ov > bv || (ov == bv && oi < bi)) { bv = ov; bi = oi; }
            }
            bi = __shfl_sync(0xFFFFFFFFu, bi, 0);

            if (lane == 0) {
                sel_idx[outoff[wid] + step] = st + bi;
                sel_sc [outoff[wid] + step] = scores[st + bi];
            }

            // Fetch best box (kk uniform across warp, srcLane holds it).
            const int kk = bi >> 5;
            const int srcLane = bi & 31;
            float BX0 = __shfl_sync(0xFFFFFFFFu, pick4(x0, kk), srcLane);
            float BY0 = __shfl_sync(0xFFFFFFFFu, pick4(y0, kk), srcLane);
            float BX1 = __shfl_sync(0xFFFFFFFFu, pick4(x1, kk), srcLane);
            float BY1 = __shfl_sync(0xFFFFFFFFu, pick4(y1, kk), srcLane);
            float areaB = (BX1 - BX0) * (BY1 - BY0);

            // Suppress IoU >= thresh (includes the selected box itself).
#pragma unroll
            for (int k = 0; k < 4; k++) {
                float ix0 = fmaxf(BX0, x0[k]);
                float iy0 = fmaxf(BY0, y0[k]);
                float ix1 = fminf(BX1, x1[k]);
                float iy1 = fminf(BY1, y1[k]);
                float inter = fmaxf(ix1 - ix0, 0.f) * fmaxf(iy1 - iy0, 0.f);
                float areaK = (x1[k] - x0[k]) * (y1[k] - y0[k]);
                float iou = inter / (areaB + areaK - inter);
                if (!(iou < thresh)) alive[k] = false;
            }
        }
    }
    __syncthreads();

    // 4. Write indices (as float) and the 7 selected scores.
    if (tid < 7) {
        out[b * 7 + tid]         = (float)sel_idx[tid];
        out[7 * B + b * 7 + tid] = sel_sc[tid];
    }
}

extern "C" void kernel_launch(void* const* d_in, const int* in_sizes, int n_in,
                              void* d_out, int out_size) {
    const float* x      = (const float*)d_in[0];
    const int*   coords = (const int*)d_in[1];
    float*       out    = (float*)d_out;

    const int B = in_sizes[0] / (CH * HW);   // 64

    dim3 grid1(B, CHUNKS);
    chan_sum_kernel<<<grid1, 196>>>(x, B);
    appm_finalize_kernel<<<B, 384>>>(coords, out, B);
}